// round 16
// baseline (speedup 1.0000x reference)
#include <cuda_runtime.h>
#include <cuda_bf16.h>
#include <math.h>

// SymLoss: B=32, C=4, N=16384, RES=32
// inputs: y_pred (32,4,4) f32, points (32,16384,3) f32,
//         voxel_grid (unused), voxel_grid_cp (32,32,32,32,3) f32
// output: 1 f32
//
// Strategy: per-batch voxel table quantized to u16 fixed-point lives in SMEM
// (192 KB/block). Gathers become LDS (conflict ~3.4) instead of fully
// divergent LDG (~32-line replay, ~66 cyc) -> breaks the L1tex replay floor.
// u16 -> float decode uses the exact 0x4B000000 magic (LOP3+FFMA, no I2F).

#define B_   32
#define C_   4
#define N_   16384
#define RES_ 32
#define VOX_ (RES_ * RES_ * RES_)   // 32768
#define RTPB_ 1024                  // reflect threads per block
#define RCHUNKS_ 4                  // blocks per batch
#define RPPT_ 4                     // points per thread (4096 per block)
#define NBLK_ (B_ * RCHUNKS_)       // 128 blocks -> single wave, 1 block/SM
#define REG_COEF_ 25.0f
#define INV16_ (1.0f / 65536.0f)

#define PTPB_ 256
#define PREP_VOX_PER_BLK_ 1024      // 256 threads x 4 voxels
#define PREP_NBLK_ ((B_ * VOX_) / PREP_VOX_PER_BLK_)   // 1024

// dynamic smem layout for reflect kernel
#define SMEM_TAB_XY 0               // u32[32768]  = 131072 B
#define SMEM_TAB_Z  131072          // u16[32768]  =  65536 B
#define SMEM_RED    196608          // float[32]
#define SMEM_PLANE  196736          // float[16]
#define SMEM_LAST   196800          // int
#define SMEM_BYTES  196864

__device__ float          g_planes[B_][C_][4];  // nhat.x, nhat.y, nhat.z, d
__device__ float          g_partial[NBLK_];
__device__ float          g_reg;
__device__ unsigned int   g_txy[B_ * VOX_];     // 4 MB: x | (y<<16), u16 fixed
__device__ unsigned short g_tz [B_ * VOX_];     // 2 MB: z, u16 fixed
__device__ unsigned int   g_count;              // zero-init; atomicInc wrap self-resets

// exact u16 -> [0,1) float: fmaf(as_float(0x4B000000|u), 2^-16, -128.0f)
__device__ __forceinline__ float u16_to_unit(unsigned int u)
{
    return fmaf(__uint_as_float(0x4B000000u | u), INV16_, -128.0f);
}

// ---------------------------------------------------------------------------
// Kernel 1: quantize voxel_grid_cp -> u16 fixed tables (coalesced via smem
// staging), AND (block 0, threads<32) planes + Gram regularizer.
// ---------------------------------------------------------------------------
__global__ __launch_bounds__(PTPB_) void prep_kernel(
    const float4* __restrict__ cp4,
    const float*  __restrict__ y_pred)
{
    __shared__ float s_stage[PREP_VOX_PER_BLK_ * 3];   // 12 KB

    const int tid   = threadIdx.x;
    const int vbase = blockIdx.x * PREP_VOX_PER_BLK_;

    // 3 perfectly coalesced float4 loads per thread (768 float4 = 3072 floats)
    const float4* src = cp4 + (size_t)vbase * 3 / 4;
    float4* s4 = (float4*)s_stage;
    #pragma unroll
    for (int k = 0; k < 3; k++)
        s4[tid + k * PTPB_] = src[tid + k * PTPB_];
    __syncthreads();

    // quantize + emit, coalesced
    #pragma unroll
    for (int k = 0; k < 4; k++) {
        int vloc = tid + k * PTPB_;
        float x = s_stage[vloc * 3 + 0];
        float y = s_stage[vloc * 3 + 1];
        float z = s_stage[vloc * 3 + 2];
        unsigned int ux = min(__float2uint_rn(x * 65536.0f), 65535u);
        unsigned int uy = min(__float2uint_rn(y * 65536.0f), 65535u);
        unsigned int uz = min(__float2uint_rn(z * 65536.0f), 65535u);
        g_txy[vbase + vloc] = ux | (uy << 16);
        g_tz [vbase + vloc] = (unsigned short)uz;
    }

    if (blockIdx.x == 0 && tid < B_) {
        int b = tid;
        float nx[C_], ny[C_], nz[C_];
        #pragma unroll
        for (int c = 0; c < C_; c++) {
            float x = y_pred[b * 16 + c * 4 + 0];
            float y = y_pred[b * 16 + c * 4 + 1];
            float z = y_pred[b * 16 + c * 4 + 2];
            float d = y_pred[b * 16 + c * 4 + 3];
            float inv = 1.0f / sqrtf(x * x + y * y + z * z);
            nx[c] = x * inv; ny[c] = y * inv; nz[c] = z * inv;
            g_planes[b][c][0] = nx[c];
            g_planes[b][c][1] = ny[c];
            g_planes[b][c][2] = nz[c];
            g_planes[b][c][3] = d;
        }
        float acc = 0.0f;
        #pragma unroll
        for (int c = 0; c < C_; c++) {
            #pragma unroll
            for (int e = 0; e < C_; e++) {
                float g = nx[c] * nx[e] + ny[c] * ny[e] + nz[c] * nz[e]
                          - (c == e ? 1.0f : 0.0f);
                acc += g * g;
            }
        }
        float reg_b = sqrtf(acc);
        #pragma unroll
        for (int off = 16; off > 0; off >>= 1)
            reg_b += __shfl_down_sync(0xFFFFFFFFu, reg_b, off);
        if (b == 0)
            g_reg = REG_COEF_ * (reg_b / (float)B_);
    }
}

// ---------------------------------------------------------------------------
// Kernel 2: SMEM-table reflection. 128 blocks x 1024 threads, 1 block/SM.
// Each block: load 192 KB batch table into smem, process 4096 points x 4
// planes with LDS gathers, deterministic reduce; last block finalizes.
// ---------------------------------------------------------------------------
__global__ __launch_bounds__(RTPB_, 1) void reflect_kernel(
    const float* __restrict__ points,
    float* __restrict__ out)
{
    extern __shared__ char smem[];
    unsigned int*   s_xy    = (unsigned int*)(smem + SMEM_TAB_XY);
    unsigned short* s_z     = (unsigned short*)(smem + SMEM_TAB_Z);
    float*          s_red   = (float*)(smem + SMEM_RED);
    float*          s_plane = (float*)(smem + SMEM_PLANE);
    int*            s_last  = (int*)(smem + SMEM_LAST);

    const int b     = blockIdx.x >> 2;        // RCHUNKS_=4
    const int chunk = blockIdx.x & 3;
    const int tid   = threadIdx.x;

    if (tid < C_ * 4)
        s_plane[tid] = ((const float*)g_planes[b])[tid];

    // load batch table into smem: 8192 + 4096 uint4, fully coalesced
    const uint4* gxy = (const uint4*)(g_txy + (size_t)b * VOX_);
    uint4* sxy4 = (uint4*)s_xy;
    #pragma unroll
    for (int k = 0; k < 8; k++)
        sxy4[tid + k * RTPB_] = __ldg(gxy + tid + k * RTPB_);
    const uint4* gz = (const uint4*)(g_tz + (size_t)b * VOX_);
    uint4* sz4 = (uint4*)s_z;
    #pragma unroll
    for (int k = 0; k < 4; k++)
        sz4[tid + k * RTPB_] = __ldg(gz + tid + k * RTPB_);
    __syncthreads();

    const float* pts = points + ((size_t)b * N_ + (size_t)chunk * (RTPB_ * RPPT_)) * 3;

    float acc = 0.0f;

    #pragma unroll
    for (int k = 0; k < RPPT_; k++) {
        const int p = tid + k * RTPB_;
        const float px = __ldg(pts + p * 3 + 0);
        const float py = __ldg(pts + p * 3 + 1);
        const float pz = __ldg(pts + p * 3 + 2);

        #pragma unroll
        for (int c = 0; c < C_; c++) {
            const float nx = s_plane[c * 4 + 0];
            const float ny = s_plane[c * 4 + 1];
            const float nz = s_plane[c * 4 + 2];
            const float d  = s_plane[c * 4 + 3];
            float dist = fmaf(px, nx, fmaf(py, ny, fmaf(pz, nz, d)));
            float t = 2.0f * dist;
            float rx = fmaf(-t, nx, px);
            float ry = fmaf(-t, ny, py);
            float rz = fmaf(-t, nz, pz);

            int ix = min(max(__float2int_rd(rx * (float)RES_), 0), RES_ - 1);
            int iy = min(max(__float2int_rd(ry * (float)RES_), 0), RES_ - 1);
            int iz = min(max(__float2int_rd(rz * (float)RES_), 0), RES_ - 1);
            int idx = (ix * RES_ + iy) * RES_ + iz;

            unsigned int w = s_xy[idx];
            float cx = u16_to_unit(w & 0xFFFFu);
            float cy = u16_to_unit(w >> 16);
            float cz = u16_to_unit((unsigned int)s_z[idx]);

            float dx = rx - cx;
            float dy = ry - cy;
            float dz = rz - cz;
            acc += sqrtf(fmaf(dx, dx, fmaf(dy, dy, dz * dz)));
        }
    }

    // deterministic block tree reduction (32 warps)
    #pragma unroll
    for (int off = 16; off > 0; off >>= 1)
        acc += __shfl_down_sync(0xFFFFFFFFu, acc, off);
    if ((tid & 31) == 0)
        s_red[tid >> 5] = acc;
    __syncthreads();
    if (tid < 32) {
        float v = s_red[tid];
        #pragma unroll
        for (int off = 16; off > 0; off >>= 1)
            v += __shfl_down_sync(0xFFFFFFFFu, v, off);
        if (tid == 0) {
            g_partial[blockIdx.x] = v;
            __threadfence();
            // atomicInc wraps to 0 after NBLK_-1 -> self-resetting across replays
            unsigned int prev = atomicInc(&g_count, NBLK_ - 1);
            s_last[0] = (prev == NBLK_ - 1) ? 1 : 0;
        }
    }
    __syncthreads();

    // last block: deterministic final reduction of all 128 partials
    if (s_last[0]) {
        float v = (tid < NBLK_) ? g_partial[tid] : 0.0f;   // first 4 warps carry data
        #pragma unroll
        for (int off = 16; off > 0; off >>= 1)
            v += __shfl_down_sync(0xFFFFFFFFu, v, off);
        if ((tid & 31) == 0 && tid < NBLK_)
            s_red[tid >> 5] = v;
        __syncthreads();
        if (tid == 0) {
            float w = s_red[0] + s_red[1] + s_red[2] + s_red[3];
            out[0] = w * (1.0f / (float)N_) + g_reg;
        }
    }
}

// ---------------------------------------------------------------------------
extern "C" void kernel_launch(void* const* d_in, const int* in_sizes, int n_in,
                              void* d_out, int out_size)
{
    const float*  y_pred  = (const float*)d_in[0];
    const float*  points  = (const float*)d_in[1];
    // d_in[2] = voxel_grid is unused by the reference math
    const float4* grid_cp = (const float4*)d_in[3];   // 12MB, float4-viewable
    float* out = (float*)d_out;

    cudaFuncSetAttribute(reflect_kernel,
                         cudaFuncAttributeMaxDynamicSharedMemorySize, SMEM_BYTES);

    prep_kernel<<<PREP_NBLK_, PTPB_>>>(grid_cp, y_pred);
    reflect_kernel<<<NBLK_, RTPB_, SMEM_BYTES>>>(points, out);
}